// round 9
// baseline (speedup 1.0000x reference)
#include <cuda_runtime.h>

// QuantumConvLayer: probs = [c^4, c^2 s^2, s^4, s^2 c^2],
// c^2 = (1+cos x)/2, s^2 = (1-cos x)/2, x = inputs[i,0].
// HBM-bound streaming: 256MB read + 256MB write (both mandatory, 512MB total;
// spec-BW lower bound = 64us, best measured kernel = 74.6us @ 6.45TB/s).
// R8: exact R5 structure (flat grid, TPB=256, RPT=4 front-batched dense
// LDG.128 reads, dense STG.128 writes) with the ONLY change being streaming
// cache hints: __ldcs on the read-once input, __stcs on the write-once output.

#define RPT 4
#define TPB 256
#define ROWS_PER_BLOCK (RPT * TPB)   // 1024

__device__ __forceinline__ float4 qprobs(float x)
{
    float cx = __cosf(x);
    float c2 = 0.5f + 0.5f * cx;   // cos^2(x/2)
    float s2 = 0.5f - 0.5f * cx;   // sin^2(x/2)
    float cs = c2 * s2;
    return make_float4(c2 * c2, cs, s2 * s2, cs);
}

__global__ void __launch_bounds__(TPB) qconv_kernel(
    const float4* __restrict__ in,  // [N] rows, 16B each; only .x (col 0) used
    float4* __restrict__ out,       // [N]
    int n)
{
    int tile = blockIdx.x * ROWS_PER_BLOCK;
    int t = threadIdx.x;

    float x[RPT];
    int row[RPT];

    // Front-batch 4 independent dense LDG.128s (warp = 512B contiguous each),
    // evict-first: data is read exactly once.
#pragma unroll
    for (int k = 0; k < RPT; k++) {
        row[k] = tile + t + TPB * k;
        x[k] = (row[k] < n) ? __ldcs(in + row[k]).x : 0.0f;
    }

    // Streaming stores: output is written once, never re-read.
#pragma unroll
    for (int k = 0; k < RPT; k++) {
        if (row[k] < n)
            __stcs(out + row[k], qprobs(x[k]));
    }
}

extern "C" void kernel_launch(void* const* d_in, const int* in_sizes, int n_in,
                              void* d_out, int out_size)
{
    const float4* in = (const float4*)d_in[0];
    float4* out = (float4*)d_out;
    int n = in_sizes[0] / 4;   // rows

    int grid = (n + ROWS_PER_BLOCK - 1) / ROWS_PER_BLOCK;
    qconv_kernel<<<grid, TPB>>>(in, out, n);
}

// round 11
// speedup vs baseline: 1.0177x; 1.0177x over previous
#include <cuda_runtime.h>

// QuantumConvLayer: probs = [c^4, c^2 s^2, s^4, s^2 c^2],
// c^2 = (1+cos x)/2, s^2 = (1-cos x)/2, x = inputs[i,0].
// HBM-bound streaming: 256MB read + 256MB write (both mandatory, 512MB;
// spec-BW lower bound 64us). FINAL = R5, best measured: 74.6us kernel,
// 6.45TB/s (80.7% of spec), reproduced 3x.
// Lever ledger: 4x coarsening + __cosf identity (win), dense LDG.128 reads
// (win); persistent single-wave (regressed), paired-row 32B/lane layout
// (regressed, 2x L1 wavefronts), streaming .cs hints (regressed, isolated
// in R8: L1 40.6->64.8%, DRAM 81.4->77.3% on sm_103a).

#define RPT 4
#define TPB 256
#define ROWS_PER_BLOCK (RPT * TPB)   // 1024

__device__ __forceinline__ float4 qprobs(float x)
{
    float cx = __cosf(x);
    float c2 = 0.5f + 0.5f * cx;   // cos^2(x/2)
    float s2 = 0.5f - 0.5f * cx;   // sin^2(x/2)
    float cs = c2 * s2;
    return make_float4(c2 * c2, cs, s2 * s2, cs);
}

__global__ void __launch_bounds__(TPB) qconv_kernel(
    const float4* __restrict__ in,  // [N] rows, 16B each; only .x (col 0) used
    float4* __restrict__ out,       // [N]
    int n)
{
    int tile = blockIdx.x * ROWS_PER_BLOCK;
    int t = threadIdx.x;

    float x[RPT];
    int row[RPT];

    // Front-batch 4 independent dense LDG.128s (warp = 512B contiguous each)
#pragma unroll
    for (int k = 0; k < RPT; k++) {
        row[k] = tile + t + TPB * k;
        x[k] = (row[k] < n) ? __ldg(in + row[k]).x : 0.0f;
    }

#pragma unroll
    for (int k = 0; k < RPT; k++) {
        if (row[k] < n)
            out[row[k]] = qprobs(x[k]);
    }
}

extern "C" void kernel_launch(void* const* d_in, const int* in_sizes, int n_in,
                              void* d_out, int out_size)
{
    const float4* in = (const float4*)d_in[0];
    float4* out = (float4*)d_out;
    int n = in_sizes[0] / 4;   // rows

    int grid = (n + ROWS_PER_BLOCK - 1) / ROWS_PER_BLOCK;
    qconv_kernel<<<grid, TPB>>>(in, out, n);
}